// round 15
// baseline (speedup 1.0000x reference)
#include <cuda_runtime.h>
#include <math.h>

// Problem constants (fixed by the dataset)
#define N_SEQ   1024
#define L_SEQ   64
#define NINP    512
#define NREL    200
#define EPS_E   32

// GEMM tiling (R6-proven stage pipeline; deep split-K for latency hiding)
#define SEQT    64
#define RELT    40
#define KSPLIT  16
#define KCHUNK  (NINP / KSPLIT)       // 32
#define KC      16
#define TGX     16
#define TGY     10
#define NTHR    (TGX * TGY)           // 160 threads

// Loss kernel
#define SEQ_PB  2
#define GRID_L  (N_SEQ / SEQ_PB)      // 512 blocks
#define DONE_TARGET GRID_L

// Scratch (no allocations allowed)
__device__ float               g_h[N_SEQ * NINP];               // 2 MB
__device__ float               g_part[KSPLIT * N_SEQ * NREL];   // 13.1 MB
__device__ double              g_logp    = 0.0;
__device__ unsigned long long  g_correct = 0ull;
__device__ unsigned int        g_done    = 0u;

// ---------------------------------------------------------------------------
// Kernel 1: h[i,:] = sum_j emb[seq[i,j], :]
// R6 geometry (measured best: 17.2us, DRAM 58%, occ 76%): 1 seq/block,
// 256 threads, float2/thread. Deeper unroll for more lines in flight.
// ---------------------------------------------------------------------------
__global__ void __launch_bounds__(256) gather_kernel(const int* __restrict__ seq,
                                                     const float* __restrict__ emb) {
    __shared__ int toks[L_SEQ];
    const int i = blockIdx.x;
    const int t = threadIdx.x;
    if (t < L_SEQ) toks[t] = seq[i * L_SEQ + t];
    __syncthreads();

    const int c = t * 2;
    float ax = 0.f, ay = 0.f;
#pragma unroll 16
    for (int j = 0; j < L_SEQ; j++) {
        const float2 v = *reinterpret_cast<const float2*>(
            emb + (size_t)toks[j] * NINP + c);
        ax += v.x;
        ay += v.y;
    }
    float2 o; o.x = ax; o.y = ay;
    *reinterpret_cast<float2*>(g_h + (size_t)i * NINP + c) = o;
}

// ---------------------------------------------------------------------------
// Kernel 2: register-tiled SGEMM, KC=16 stage pipeline, KSPLIT=16.
// Grid 16 x 5 x 16 = 1280 blocks, 160 threads, 4x4 accumulators.
// ---------------------------------------------------------------------------
__global__ void __launch_bounds__(NTHR) sgemm_kernel(const float* __restrict__ W) {
    __shared__ float h_s[KC][SEQT];   // 4 KB
    __shared__ float w_s[KC][RELT];   // 2.5 KB

    const int tid = threadIdx.x;
    const int sx  = tid % TGX;
    const int ry  = tid / TGX;

    const int seqBase = blockIdx.x * SEQT;
    const int relBase = blockIdx.y * RELT;
    const int kb0     = blockIdx.z * KCHUNK;

    float acc[4][4];
#pragma unroll
    for (int a = 0; a < 4; a++)
#pragma unroll
        for (int c = 0; c < 4; c++) acc[a][c] = 0.f;

#pragma unroll
    for (int st = 0; st < KCHUNK / KC; st++) {       // 2 stages
        const int kb = kb0 + st * KC;

        for (int i = tid; i < (SEQT * KC) / 4; i += NTHR) {
            const int s  = i >> 2;
            const int k4 = i & 3;
            const float4 v = *reinterpret_cast<const float4*>(
                g_h + (size_t)(seqBase + s) * NINP + kb + k4 * 4);
            h_s[k4 * 4 + 0][s] = v.x;
            h_s[k4 * 4 + 1][s] = v.y;
            h_s[k4 * 4 + 2][s] = v.z;
            h_s[k4 * 4 + 3][s] = v.w;
        }
        {
            const int r  = tid >> 2;
            const int k4 = tid & 3;
            const float4 v = *reinterpret_cast<const float4*>(
                W + (size_t)(relBase + r) * NINP + kb + k4 * 4);
            w_s[k4 * 4 + 0][r] = v.x;
            w_s[k4 * 4 + 1][r] = v.y;
            w_s[k4 * 4 + 2][r] = v.z;
            w_s[k4 * 4 + 3][r] = v.w;
        }
        __syncthreads();

#pragma unroll
        for (int k = 0; k < KC; k++) {
            const float4 a = *reinterpret_cast<const float4*>(&h_s[k][sx * 4]);
            const float4 w = *reinterpret_cast<const float4*>(&w_s[k][ry * 4]);
            const float av[4] = {a.x, a.y, a.z, a.w};
            const float wv[4] = {w.x, w.y, w.z, w.w};
#pragma unroll
            for (int i = 0; i < 4; i++)
#pragma unroll
                for (int j = 0; j < 4; j++)
                    acc[i][j] += av[i] * wv[j];
        }
        __syncthreads();
    }

    float* base = g_part + ((size_t)blockIdx.z * N_SEQ + seqBase + sx * 4) * NREL
                  + relBase + ry * 4;
#pragma unroll
    for (int i = 0; i < 4; i++) {
        float4 o;
        o.x = acc[i][0]; o.y = acc[i][1]; o.z = acc[i][2]; o.w = acc[i][3];
        *reinterpret_cast<float4*>(base + (size_t)i * NREL) = o;
    }
}

// ---------------------------------------------------------------------------
// Kernel 3: split-K reduce + bias, mask build, fused loss + acc reduction.
// 512 blocks x 256 threads, 2 seqs per block.
// ---------------------------------------------------------------------------
__global__ void __launch_bounds__(256) loss_kernel(const int* __restrict__ rel,
                                                   const float* __restrict__ b,
                                                   float* __restrict__ out) {
    __shared__ unsigned char mask_s[SEQ_PB][256];
    __shared__ float         red_f[256];
    __shared__ int           red_i[256];

    const int tid  = threadIdx.x;
    const int seq0 = blockIdx.x * SEQ_PB;

    // Zero mask (2*256 bytes = 128 ints)
    if (tid < (SEQ_PB * 256) / 4)
        reinterpret_cast<int*>(&mask_s[0][0])[tid] = 0;
    __syncthreads();

    if (tid < SEQ_PB * EPS_E) {
        const int r = rel[seq0 * EPS_E + tid];
        mask_s[tid >> 5][r] = 1;
    }
    __syncthreads();

    float lp   = 0.f;
    int   corr = 0;

    if (tid < NREL) {
        const float bb = b[tid];
#pragma unroll
        for (int s = 0; s < SEQ_PB; s++) {
            const size_t idx = (size_t)(seq0 + s) * NREL + tid;
            float x = bb;
#pragma unroll
            for (int ks = 0; ks < KSPLIT; ks++)
                x += g_part[(size_t)ks * N_SEQ * NREL + idx];

            const bool msk = (mask_s[s][tid] != 0);
            float val;
            if (msk) {
                val = fminf(x, 0.f) - log1pf(expf(-fabsf(x)));
            } else {
                val = logf(1.0f / (1.0f + expf(x)) + 1e-5f);
            }
            lp   += val;
            corr += ((x > 0.5f) == msk) ? 1 : 0;
        }
    }

    red_f[tid] = lp;
    red_i[tid] = corr;
    __syncthreads();
#pragma unroll
    for (int st = 128; st > 0; st >>= 1) {
        if (tid < st) {
            red_f[tid] += red_f[tid + st];
            red_i[tid] += red_i[tid + st];
        }
        __syncthreads();
    }

    if (tid == 0) {
        atomicAdd(&g_logp, (double)red_f[0]);
        atomicAdd(&g_correct, (unsigned long long)red_i[0]);
        __threadfence();
        const unsigned int done = atomicAdd(&g_done, 1u);
        if (done == (unsigned int)(DONE_TARGET - 1)) {
            const double logp  = g_logp / (double)N_SEQ;
            const double acc_v = (double)g_correct / ((double)N_SEQ * (double)NREL);
            out[0] = (float)logp;
            out[1] = (float)acc_v;
            g_logp    = 0.0;
            g_correct = 0ull;
            g_done    = 0u;
        }
    }
}

// ---------------------------------------------------------------------------
// Single-stream serial graph.
// ---------------------------------------------------------------------------
extern "C" void kernel_launch(void* const* d_in, const int* in_sizes, int n_in,
                              void* d_out, int out_size) {
    const int*   seq = (const int*)d_in[0];
    const int*   rel = (const int*)d_in[2];
    const float* emb = (const float*)d_in[3];
    const float* W   = (const float*)d_in[4];
    const float* b   = (const float*)d_in[5];
    float*       out = (float*)d_out;

    gather_kernel<<<N_SEQ, 256>>>(seq, emb);
    dim3 gg(N_SEQ / SEQT, NREL / RELT, KSPLIT);   // 16 x 5 x 16 = 1280 blocks
    sgemm_kernel<<<gg, NTHR>>>(W);
    loss_kernel<<<GRID_L, 256>>>(rel, b, out);
}

// round 16
// speedup vs baseline: 1.4687x; 1.4687x over previous
#include <cuda_runtime.h>
#include <math.h>

// Problem constants (fixed by the dataset)
#define N_SEQ   1024
#define L_SEQ   64
#define NINP    512
#define NREL    200
#define EPS_E   32

// GEMM tiling (measured-best: KC=16 stage pipeline, KSPLIT=8, 640 blocks)
#define SEQT    64
#define RELT    40
#define KSPLIT  8
#define KCHUNK  (NINP / KSPLIT)       // 64
#define KC      16
#define TGX     16
#define TGY     10
#define NTHR    (TGX * TGY)           // 160 threads

// Loss kernel (measured-best: 4 seqs per block, 256 blocks)
#define SEQ_PB  4
#define GRID_L  (N_SEQ / SEQ_PB)      // 256 blocks
#define DONE_TARGET GRID_L

// Scratch (no allocations allowed)
__device__ float               g_h[N_SEQ * NINP];               // 2 MB
__device__ float               g_part[KSPLIT * N_SEQ * NREL];   // 6.55 MB
__device__ double              g_logp    = 0.0;
__device__ unsigned long long  g_correct = 0ull;
__device__ unsigned int        g_done    = 0u;

// ---------------------------------------------------------------------------
// Kernel 1: h[i,:] = sum_j emb[seq[i,j], :]
// R6 exact geometry (measured 17.2us / DRAM 58% / occ 76% repeatedly):
// 1 seq per block, 256 threads, float2 per thread, unroll 8.
// ---------------------------------------------------------------------------
__global__ void __launch_bounds__(256) gather_kernel(const int* __restrict__ seq,
                                                     const float* __restrict__ emb) {
    __shared__ int toks[L_SEQ];
    const int i = blockIdx.x;
    const int t = threadIdx.x;
    if (t < L_SEQ) toks[t] = seq[i * L_SEQ + t];
    __syncthreads();

    const int c = t * 2;
    float ax = 0.f, ay = 0.f;
#pragma unroll 8
    for (int j = 0; j < L_SEQ; j++) {
        const float2 v = *reinterpret_cast<const float2*>(
            emb + (size_t)toks[j] * NINP + c);
        ax += v.x;
        ay += v.y;
    }
    float2 o; o.x = ax; o.y = ay;
    *reinterpret_cast<float2*>(g_h + (size_t)i * NINP + c) = o;
}

// ---------------------------------------------------------------------------
// Kernel 2: register-tiled SGEMM, KC=16 stage pipeline, KSPLIT=8.
// Grid 16 x 5 x 8 = 640 blocks, 160 threads, 4x4 accumulators.
// ---------------------------------------------------------------------------
__global__ void __launch_bounds__(NTHR) sgemm_kernel(const float* __restrict__ W) {
    __shared__ float h_s[KC][SEQT];   // 4 KB
    __shared__ float w_s[KC][RELT];   // 2.5 KB

    const int tid = threadIdx.x;
    const int sx  = tid % TGX;
    const int ry  = tid / TGX;

    const int seqBase = blockIdx.x * SEQT;
    const int relBase = blockIdx.y * RELT;
    const int kb0     = blockIdx.z * KCHUNK;

    float acc[4][4];
#pragma unroll
    for (int a = 0; a < 4; a++)
#pragma unroll
        for (int c = 0; c < 4; c++) acc[a][c] = 0.f;

#pragma unroll
    for (int st = 0; st < KCHUNK / KC; st++) {       // 4 stages
        const int kb = kb0 + st * KC;

        for (int i = tid; i < (SEQT * KC) / 4; i += NTHR) {
            const int s  = i >> 2;
            const int k4 = i & 3;
            const float4 v = __ldg(reinterpret_cast<const float4*>(
                g_h + (size_t)(seqBase + s) * NINP + kb + k4 * 4));
            h_s[k4 * 4 + 0][s] = v.x;
            h_s[k4 * 4 + 1][s] = v.y;
            h_s[k4 * 4 + 2][s] = v.z;
            h_s[k4 * 4 + 3][s] = v.w;
        }
        {
            const int r  = tid >> 2;
            const int k4 = tid & 3;
            const float4 v = __ldg(reinterpret_cast<const float4*>(
                W + (size_t)(relBase + r) * NINP + kb + k4 * 4));
            w_s[k4 * 4 + 0][r] = v.x;
            w_s[k4 * 4 + 1][r] = v.y;
            w_s[k4 * 4 + 2][r] = v.z;
            w_s[k4 * 4 + 3][r] = v.w;
        }
        __syncthreads();

#pragma unroll
        for (int k = 0; k < KC; k++) {
            const float4 a = *reinterpret_cast<const float4*>(&h_s[k][sx * 4]);
            const float4 w = *reinterpret_cast<const float4*>(&w_s[k][ry * 4]);
            const float av[4] = {a.x, a.y, a.z, a.w};
            const float wv[4] = {w.x, w.y, w.z, w.w};
#pragma unroll
            for (int i = 0; i < 4; i++)
#pragma unroll
                for (int j = 0; j < 4; j++)
                    acc[i][j] += av[i] * wv[j];
        }
        __syncthreads();
    }

    float* base = g_part + ((size_t)blockIdx.z * N_SEQ + seqBase + sx * 4) * NREL
                  + relBase + ry * 4;
#pragma unroll
    for (int i = 0; i < 4; i++) {
        float4 o;
        o.x = acc[i][0]; o.y = acc[i][1]; o.z = acc[i][2]; o.w = acc[i][3];
        *reinterpret_cast<float4*>(base + (size_t)i * NREL) = o;
    }
}

// ---------------------------------------------------------------------------
// Kernel 3: split-K reduce + bias, mask build, fused loss + acc reduction.
// Partial loads batched (all 8 issued before summing) for MLP.
// ---------------------------------------------------------------------------
__global__ void __launch_bounds__(256) loss_kernel(const int* __restrict__ rel,
                                                   const float* __restrict__ b,
                                                   float* __restrict__ out) {
    __shared__ unsigned char mask_s[SEQ_PB][256];
    __shared__ float         red_f[256];
    __shared__ int           red_i[256];

    const int tid  = threadIdx.x;
    const int seq0 = blockIdx.x * SEQ_PB;

    reinterpret_cast<int*>(&mask_s[0][0])[tid] = 0;
    __syncthreads();

    if (tid < SEQ_PB * EPS_E) {
        const int r = rel[seq0 * EPS_E + tid];
        mask_s[tid >> 5][r] = 1;
    }
    __syncthreads();

    float lp   = 0.f;
    int   corr = 0;

    if (tid < NREL) {
        const float bb = b[tid];
#pragma unroll
        for (int s = 0; s < SEQ_PB; s++) {
            const size_t idx = (size_t)(seq0 + s) * NREL + tid;
            // Batch all split loads first (MLP), then sum
            float p[KSPLIT];
#pragma unroll
            for (int ks = 0; ks < KSPLIT; ks++)
                p[ks] = g_part[(size_t)ks * N_SEQ * NREL + idx];
            float x = bb;
#pragma unroll
            for (int ks = 0; ks < KSPLIT; ks++) x += p[ks];

            const bool msk = (mask_s[s][tid] != 0);
            float val;
            if (msk) {
                val = fminf(x, 0.f) - log1pf(expf(-fabsf(x)));
            } else {
                val = logf(1.0f / (1.0f + expf(x)) + 1e-5f);
            }
            lp   += val;
            corr += ((x > 0.5f) == msk) ? 1 : 0;
        }
    }

    red_f[tid] = lp;
    red_i[tid] = corr;
    __syncthreads();
#pragma unroll
    for (int st = 128; st > 0; st >>= 1) {
        if (tid < st) {
            red_f[tid] += red_f[tid + st];
            red_i[tid] += red_i[tid + st];
        }
        __syncthreads();
    }

    if (tid == 0) {
        atomicAdd(&g_logp, (double)red_f[0]);
        atomicAdd(&g_correct, (unsigned long long)red_i[0]);
        __threadfence();
        const unsigned int done = atomicAdd(&g_done, 1u);
        if (done == (unsigned int)(DONE_TARGET - 1)) {
            const double logp  = g_logp / (double)N_SEQ;
            const double acc_v = (double)g_correct / ((double)N_SEQ * (double)NREL);
            out[0] = (float)logp;
            out[1] = (float)acc_v;
            g_logp    = 0.0;
            g_correct = 0ull;
            g_done    = 0u;
        }
    }
}

// ---------------------------------------------------------------------------
// Single-stream serial graph.
// ---------------------------------------------------------------------------
extern "C" void kernel_launch(void* const* d_in, const int* in_sizes, int n_in,
                              void* d_out, int out_size) {
    const int*   seq = (const int*)d_in[0];
    const int*   rel = (const int*)d_in[2];
    const float* emb = (const float*)d_in[3];
    const float* W   = (const float*)d_in[4];
    const float* b   = (const float*)d_in[5];
    float*       out = (float*)d_out;

    gather_kernel<<<N_SEQ, 256>>>(seq, emb);
    dim3 gg(N_SEQ / SEQT, NREL / RELT, KSPLIT);   // 16 x 5 x 8 = 640 blocks
    sgemm_kernel<<<gg, NTHR>>>(W);
    loss_kernel<<<GRID_L, 256>>>(rel, b, out);
}